// round 14
// baseline (speedup 1.0000x reference)
#include <cuda_runtime.h>
#include <cuda_bf16.h>
#include <cuda_pipeline.h>
#include <math.h>
#include <float.h>

// R14: gap-based two-pass VQ argmin with COMPACTED ambiguous-row rescue.
// vs R13 (regressed): heterogeneous work is never mixed under one barrier.
//  k_approx: HMMA approx scores; per-row (min1,min2,argmin); decided rows
//            (gap > GAP) finalize immediately into g_code; ambiguous rows
//            are appended to a compacted global list.
//  k_resc:   warp-stride over the compacted list only (~30% of rows),
//            lane-per-candidate bit-exact R7 chains, winner -> g_code.
//  k_final:  uniform coalesced epilogue for all rows (reads g_code).
// Invariant: final code decision bit-identical to R7.

#define NROWS 131072
#define D     128
#define M     1024
#define DECAYF 0.999f
#define EPSF   1e-5f

#define OFF_Q     0L
#define OFF_CODES 16777216L
#define OFF_LOSS  16908288L
#define OFF_PERP  16908289L
#define OFF_EMB   16908290L
#define OFF_CNT   17039362L
#define OFF_W     17040386L
#define OUT_TOTAL 17171458L

#define CHUNKS   8
#define CN       128
#define MARGIN   2e-3f      // candidate window (validated R11/R12/R13)
#define GAP      1.5e-3f    // decided threshold (validated R13: decisions exact)
#define AMB_BLOCKS 1024

// Scratch
__device__ float g_e2[M];
__device__ float g_x2[NROWS];
__device__ float g_counts[M];
__device__ float g_dw[M * D];
__device__ float g_loss;
__device__ __nv_bfloat16 g_ebf[M * D];
__device__ int            g_code[NROWS];
__device__ unsigned short g_cand[(long)NROWS * 32];  // 16 slots per half
__device__ int            g_ambcount;
__device__ unsigned       g_amblist[NROWS];          // bit31 = overflow

__device__ __forceinline__ unsigned smem_u32(const void* p) {
    unsigned a;
    asm("{ .reg .u64 t; cvta.to.shared.u64 t, %1; cvt.u32.u64 %0, t; }"
        : "=r"(a) : "l"(p));
    return a;
}

// ---------------------------------------------------------------------------
// Prep: zero scratch, exact ||e||^2, bf16 embedding image
// ---------------------------------------------------------------------------
__global__ void k_prep(const float* __restrict__ emb) {
    int i = blockIdx.x * 256 + threadIdx.x;
    if (i < M * D) {
        g_dw[i] = 0.0f;
        g_ebf[i] = __float2bfloat16_rn(emb[i]);
    }
    if (i < M) {
        g_counts[i] = 0.0f;
        const float* row = emb + i * D;
        float s = 0.0f;
#pragma unroll 8
        for (int d = 0; d < D; d++) { float v = row[d]; s = __fadd_rn(s, __fmul_rn(v, v)); }
        g_e2[i] = s;
    }
    if (i == 0) { g_loss = 0.0f; g_ambcount = 0; }
}

// ---------------------------------------------------------------------------
// ||x||^2 (binade carrier; validated R7)
// ---------------------------------------------------------------------------
__global__ __launch_bounds__(128)
void k_x2(const float* __restrict__ x) {
    __shared__ float sw[2][2];
    const int rsub = threadIdx.x >> 6;
    const int t    = threadIdx.x & 63;
    const long row = (long)blockIdx.x * 2 + rsub;
    float2 v = ((const float2*)(x + row * D))[t];
    float p = __fadd_rn(__fmul_rn(v.x, v.x), __fmul_rn(v.y, v.y));
#pragma unroll
    for (int off = 16; off > 0; off >>= 1)
        p = __fadd_rn(p, __shfl_down_sync(0xffffffffu, p, off));
    if ((t & 31) == 0) sw[rsub][t >> 5] = p;
    __syncthreads();
    if (t == 0) g_x2[row] = __fadd_rn(sw[rsub][0], sw[rsub][1]);
}

// ---------------------------------------------------------------------------
// Pass A: mma.sync bf16 approx scores; per-row (min1,min2,argmin) + cands.
// CTA 256 thr / 128 rows. Scan: thread = (row = tid&127, half = tid>>7).
// ---------------------------------------------------------------------------
#define XES 136
#define SCS 130
#define SM_XS_B   (128 * XES * 2)
#define SM_EB_OFF SM_XS_B
#define SM_EB_B   (128 * XES * 2)
#define SM_SC_OFF (SM_EB_OFF + SM_EB_B)
#define SM_SC_B   (128 * SCS * 2)
#define SM_E2_OFF (SM_SC_OFF + SM_SC_B)
#define SMEMA_BYTES (SM_E2_OFF + 4096)   // 107008

#define LDMX4(r0, r1, r2, r3, a) \
    asm volatile("ldmatrix.sync.aligned.m8n8.x4.shared.b16 {%0,%1,%2,%3}, [%4];" \
        : "=r"(r0), "=r"(r1), "=r"(r2), "=r"(r3) : "r"(a))

#define MMA16816(c, a, b) \
    asm volatile("mma.sync.aligned.m16n8k16.row.col.f32.bf16.bf16.f32 " \
        "{%0,%1,%2,%3}, {%4,%5,%6,%7}, {%8,%9}, {%0,%1,%2,%3};" \
        : "+f"((c)[0]), "+f"((c)[1]), "+f"((c)[2]), "+f"((c)[3]) \
        : "r"((a)[0]), "r"((a)[1]), "r"((a)[2]), "r"((a)[3]), \
          "r"((b)[0]), "r"((b)[1]))

__global__ __launch_bounds__(256, 2)
void k_approx(const float* __restrict__ x) {
    extern __shared__ unsigned char sm[];
    __nv_bfloat16* xs = (__nv_bfloat16*)sm;
    __nv_bfloat16* eb = (__nv_bfloat16*)(sm + SM_EB_OFF);
    __nv_bfloat16* scores = (__nv_bfloat16*)(sm + SM_SC_OFF);
    float* e2s = (float*)(sm + SM_E2_OFF);
    const unsigned xs_a = smem_u32(xs);
    const unsigned eb_a = smem_u32(eb);

    const int tid = threadIdx.x, w = tid >> 5, lane = tid & 31;
    const int R0 = blockIdx.x * 128;

    for (int i = tid; i < 1024; i += 256) e2s[i] = g_e2[i];

    {   // prefetch e chunk 0
        const unsigned char* src = (const unsigned char*)g_ebf;
        unsigned char* dst = (unsigned char*)eb;
        for (int i = tid; i < 2048; i += 256) {
            int r = i >> 4, o = (i & 15) * 16;
            __pipeline_memcpy_async(dst + r * 272 + o, src + r * 256 + o, 16);
        }
        __pipeline_commit();
    }

    {   // x tile -> bf16 smem [row][k]
        const float4* x4 = (const float4*)x;
        for (int i = tid; i < 4096; i += 256) {
            int r = i >> 5, kg = i & 31;
            float4 v = x4[(long)(R0 + r) * 32 + kg];
            __nv_bfloat162 p0 = __floats2bfloat162_rn(v.x, v.y);
            __nv_bfloat162 p1 = __floats2bfloat162_rn(v.z, v.w);
            *(uint2*)&xs[r * XES + kg * 4] =
                make_uint2(*(unsigned*)&p0, *(unsigned*)&p1);
        }
    }

    const int rg = w >> 1;                 // MMA row group (32 rows)
    const int cg = w & 1;                  // MMA code half (64 codes)
    const int rbase = rg * 32;

    // scan state: thread = (srow, half)
    const int srow = tid & 127, half = tid >> 7;
    float rm = FLT_MAX, rm2 = FLT_MAX;
    int am = 0, cnt = 0;
    unsigned short* crow = g_cand + ((long)(R0 + srow)) * 32 + half * 16;

    for (int ch = 0; ch < CHUNKS; ch++) {
        __pipeline_wait_prior(0);
        __syncthreads();                   // eb(ch) ready; prev scan done

        float acc[2][8][4];
#pragma unroll
        for (int mt = 0; mt < 2; mt++)
#pragma unroll
            for (int nt = 0; nt < 8; nt++)
#pragma unroll
                for (int q = 0; q < 4; q++) acc[mt][nt][q] = 0.0f;

#pragma unroll
        for (int ks = 0; ks < 8; ks++) {
            unsigned a[2][4];
#pragma unroll
            for (int mt = 0; mt < 2; mt++) {
                int row = rbase + mt * 16 + (lane & 7) + ((lane >> 3) & 1) * 8;
                int ko  = ks * 16 + (lane >> 4) * 8;
                unsigned ad = xs_a + (unsigned)(row * XES + ko) * 2;
                LDMX4(a[mt][0], a[mt][1], a[mt][2], a[mt][3], ad);
            }
            unsigned b[8][2];
#pragma unroll
            for (int p = 0; p < 4; p++) {
                int g = lane >> 3, ri = lane & 7;
                int code = cg * 64 + p * 16 + (g >> 1) * 8 + ri;
                int ko   = ks * 16 + (g & 1) * 8;
                unsigned ad = eb_a + (unsigned)(code * XES + ko) * 2;
                LDMX4(b[2 * p][0], b[2 * p][1], b[2 * p + 1][0], b[2 * p + 1][1], ad);
            }
#pragma unroll
            for (int mt = 0; mt < 2; mt++)
#pragma unroll
                for (int nt = 0; nt < 8; nt++)
                    MMA16816(acc[mt][nt], a[mt], b[nt]);
        }

        // scores (bf16) = e2 - 2*dot
#pragma unroll
        for (int mt = 0; mt < 2; mt++)
#pragma unroll
            for (int nt = 0; nt < 8; nt++) {
                int row = rbase + mt * 16 + (lane >> 2);
                int col = cg * 64 + nt * 8 + (lane & 3) * 2;
                float e2a = e2s[ch * CN + col], e2b = e2s[ch * CN + col + 1];
                __nv_bfloat162 p0 = __floats2bfloat162_rn(
                    fmaf(-2.0f, acc[mt][nt][0], e2a),
                    fmaf(-2.0f, acc[mt][nt][1], e2b));
                __nv_bfloat162 p1 = __floats2bfloat162_rn(
                    fmaf(-2.0f, acc[mt][nt][2], e2a),
                    fmaf(-2.0f, acc[mt][nt][3], e2b));
                *(unsigned*)&scores[row * SCS + col] = *(unsigned*)&p0;
                *(unsigned*)&scores[(row + 8) * SCS + col] = *(unsigned*)&p1;
            }
        __syncthreads();                   // eb free; scores ready

        // prefetch chunk ch+1 (overlaps scan)
        if (ch + 1 < CHUNKS) {
            const unsigned char* src =
                (const unsigned char*)g_ebf + (ch + 1) * CN * 256;
            unsigned char* dst = (unsigned char*)eb;
            for (int i = tid; i < 2048; i += 256) {
                int r = i >> 4, o = (i & 15) * 16;
                __pipeline_memcpy_async(dst + r * 272 + o, src + r * 256 + o, 16);
            }
        }
        __pipeline_commit();

        // scan: each thread scans 64 codes of its half
        {
            const __nv_bfloat16* sr = &scores[srow * SCS + half * 64];
            const int cbase = ch * CN + half * 64;
#pragma unroll 4
            for (int c = 0; c < 64; c++) {
                float s = __bfloat162float(sr[c]);
                if (s < rm + MARGIN) {
                    if (cnt < 16) crow[cnt] = (unsigned short)(cbase + c);
                    cnt++;
                }
                if (s < rm) { rm2 = rm; rm = s; am = cbase + c; }
                else if (s < rm2) rm2 = s;
            }
        }
    }

    // sentinel-fill unused slots
    for (int i = (cnt < 16 ? cnt : 16); i < 16; i++) crow[i] = 0xFFFF;

    // combine halves -> per-row decision + compaction
    __syncthreads();
    float* c_rm  = (float*)scores;
    float* c_rm2 = c_rm + 256;
    int*   c_am  = (int*)(c_rm2 + 256);
    int*   c_cnt = c_am + 256;
    c_rm[tid] = rm; c_rm2[tid] = rm2; c_am[tid] = am; c_cnt[tid] = cnt;
    __syncthreads();
    if (tid < 128) {
        float rmA = c_rm[tid],  rmB = c_rm[tid + 128];
        float r2A = c_rm2[tid], r2B = c_rm2[tid + 128];
        int   amA = c_am[tid],  amB = c_am[tid + 128];
        float min1, min2; int amW;
        if (rmA <= rmB) { min1 = rmA; amW = amA; min2 = fminf(r2A, rmB); }
        else            { min1 = rmB; amW = amB; min2 = fminf(r2B, rmA); }
        g_code[R0 + tid] = amW;            // approx winner (final if decided)
        if (min2 - min1 <= GAP) {
            int cA = c_cnt[tid], cB = c_cnt[tid + 128];
            unsigned flag = (cA <= 16 && cB <= 16) ? 0u : 0x80000000u;
            int pos = atomicAdd(&g_ambcount, 1);
            g_amblist[pos] = (unsigned)(R0 + tid) | flag;
        }
    }
}

// ---------------------------------------------------------------------------
// Rescue: warp-stride over the compacted ambiguous list. No barriers.
// Bit-exact R7 chain: serial ascending-k fp32 FMA; s = fl(fl(e2+x2)-2*dot);
// lexicographic (s, code) selection = first-index argmin.
// ---------------------------------------------------------------------------
__global__ __launch_bounds__(256)
void k_resc(const float* __restrict__ x, const float* __restrict__ emb) {
    const int gw = (blockIdx.x * 256 + threadIdx.x) >> 5;
    const int lane = threadIdx.x & 31;
    const int n = g_ambcount;
    for (int i = gw; i < n; i += AMB_BLOCKS * 8) {
        unsigned e = g_amblist[i];
        const long row = (long)(e & 0x7fffffffu);
        const bool overflow = (e & 0x80000000u) != 0;
        const float4* xr = (const float4*)(x + row * 128);
        const float x2v = g_x2[row];
        float best = FLT_MAX; int bcode = 0x7fffffff;
        if (!overflow) {
            int c16 = g_cand[row * 32 + lane];
            if (c16 != 0xFFFF) {
                const float4* er = (const float4*)(emb + (long)c16 * 128);
                float acc = 0.0f;
#pragma unroll 8
                for (int k = 0; k < 32; k++) {
                    float4 a = xr[k], b = er[k];
                    acc = fmaf(a.x, b.x, acc);
                    acc = fmaf(a.y, b.y, acc);
                    acc = fmaf(a.z, b.z, acc);
                    acc = fmaf(a.w, b.w, acc);
                }
                best = __fadd_rn(__fadd_rn(g_e2[c16], x2v),
                                 __fmul_rn(-2.0f, acc));
                bcode = c16;
            }
        } else {
            for (int t = 0; t < 32; t++) {
                int c = lane + t * 32;
                const float4* er = (const float4*)(emb + (long)c * 128);
                float acc = 0.0f;
#pragma unroll 8
                for (int k = 0; k < 32; k++) {
                    float4 a = xr[k], b = er[k];
                    acc = fmaf(a.x, b.x, acc);
                    acc = fmaf(a.y, b.y, acc);
                    acc = fmaf(a.z, b.z, acc);
                    acc = fmaf(a.w, b.w, acc);
                }
                float s = __fadd_rn(__fadd_rn(g_e2[c], x2v),
                                    __fmul_rn(-2.0f, acc));
                if (s < best || (s == best && c < bcode)) { best = s; bcode = c; }
            }
        }
#pragma unroll
        for (int o = 16; o > 0; o >>= 1) {
            float ob = __shfl_xor_sync(0xffffffffu, best, o);
            int   oc = __shfl_xor_sync(0xffffffffu, bcode, o);
            if (ob < best || (ob == best && oc < bcode)) { best = ob; bcode = oc; }
        }
        if (lane == 0) g_code[row] = bcode;
    }
}

// ---------------------------------------------------------------------------
// Final epilogue: uniform work, warp per row, lane per float4.
// ---------------------------------------------------------------------------
__global__ __launch_bounds__(256)
void k_final(const float* __restrict__ x, const float* __restrict__ emb,
             float* __restrict__ out_q, float* __restrict__ out_codes,
             int write_aux) {
    __shared__ float sl[8];
    const int w = threadIdx.x >> 5, lane = threadIdx.x & 31;
    const long row = (long)blockIdx.x * 8 + w;
    const int code = g_code[row];

    float4 xv = ((const float4*)x)[row * 32 + lane];
    float4 qv = ((const float4*)emb)[(long)code * 32 + lane];
    float4 o;
    o.x = __fadd_rn(xv.x, __fsub_rn(qv.x, xv.x));
    o.y = __fadd_rn(xv.y, __fsub_rn(qv.y, xv.y));
    o.z = __fadd_rn(xv.z, __fsub_rn(qv.z, xv.z));
    o.w = __fadd_rn(xv.w, __fsub_rn(qv.w, xv.w));
    ((float4*)out_q)[row * 32 + lane] = o;

    float dx = xv.x - qv.x, dy = xv.y - qv.y, dz = xv.z - qv.z, dw_ = xv.w - qv.w;
    float lsum = dx * dx + dy * dy + dz * dz + dw_ * dw_;

    float* dwp = &g_dw[code * 128 + lane * 4];
    atomicAdd(dwp + 0, xv.x);
    atomicAdd(dwp + 1, xv.y);
    atomicAdd(dwp + 2, xv.z);
    atomicAdd(dwp + 3, xv.w);

    if (lane == 0) {
        atomicAdd(&g_counts[code], 1.0f);
        if (write_aux) out_codes[row] = (float)code;
    }
#pragma unroll
    for (int o2 = 16; o2 > 0; o2 >>= 1)
        lsum += __shfl_xor_sync(0xffffffffu, lsum, o2);
    if (lane == 0) sl[w] = lsum;
    __syncthreads();
    if (threadIdx.x == 0) {
        float t = 0.0f;
#pragma unroll
        for (int i = 0; i < 8; i++) t += sl[i];
        atomicAdd(&g_loss, t);
    }
}

// ---------------------------------------------------------------------------
// EMA scalar part (validated R7)
// ---------------------------------------------------------------------------
__global__ void k_ema1(const float* __restrict__ ema_count,
                       float* __restrict__ out_count,
                       float* __restrict__ out_loss,
                       float* __restrict__ out_perp) {
    __shared__ float sred[1024];
    int m = threadIdx.x;
    float cnt = g_counts[m];
    float raw = DECAYF * ema_count[m] + (1.0f - DECAYF) * cnt;
    sred[m] = raw;
    __syncthreads();
    for (int s = 512; s > 0; s >>= 1) {
        if (m < s) sred[m] += sred[m + s];
        __syncthreads();
    }
    float n = sred[0];
    __syncthreads();
    float newc = (raw + EPSF) / (n + 1024.0f * EPSF) * n;
    out_count[m] = newc;

    float p = cnt * (1.0f / 131072.0f);
    sred[m] = -p * logf(p + 1e-10f);
    __syncthreads();
    for (int s = 512; s > 0; s >>= 1) {
        if (m < s) sred[m] += sred[m + s];
        __syncthreads();
    }
    if (m == 0) {
        *out_perp = expf(sred[0]);
        *out_loss = 0.25f * g_loss * (1.0f / 16777216.0f);
    }
}

// ---------------------------------------------------------------------------
// EMA vector part (validated R7)
// ---------------------------------------------------------------------------
__global__ void k_ema2(const float* __restrict__ ema_weight,
                       const float* __restrict__ newc,
                       float* __restrict__ out_w,
                       float* __restrict__ out_emb) {
    int i = blockIdx.x * 256 + threadIdx.x;
    float w = DECAYF * ema_weight[i] + (1.0f - DECAYF) * g_dw[i];
    out_w[i] = w;
    out_emb[i] = w / newc[i >> 7];
}

// ---------------------------------------------------------------------------
extern "C" void kernel_launch(void* const* d_in, const int* in_sizes, int n_in,
                              void* d_out, int out_size) {
    const float* x          = (const float*)d_in[0];
    const float* emb        = (const float*)d_in[1];
    const float* ema_count  = (const float*)d_in[2];
    const float* ema_weight = (const float*)d_in[3];
    float* out = (float*)d_out;

    const int full = (out_size >= (int)OUT_TOTAL) ? 1 : 0;

    cudaFuncSetAttribute(k_approx, cudaFuncAttributeMaxDynamicSharedMemorySize,
                         SMEMA_BYTES);

    k_prep<<<512, 256>>>(emb);
    k_x2<<<NROWS / 2, 128>>>(x);
    k_approx<<<NROWS / 128, 256, SMEMA_BYTES>>>(x);
    k_resc<<<AMB_BLOCKS, 256>>>(x, emb);
    k_final<<<NROWS / 8, 256>>>(x, emb, out + OFF_Q,
                                full ? (out + OFF_CODES) : (out + OFF_Q), full);
    if (full) {
        k_ema1<<<1, 1024>>>(ema_count, out + OFF_CNT, out + OFF_LOSS,
                            out + OFF_PERP);
        k_ema2<<<512, 256>>>(ema_weight, out + OFF_CNT, out + OFF_W,
                             out + OFF_EMB);
    }
}

// round 15
// speedup vs baseline: 1.7654x; 1.7654x over previous
#include <cuda_runtime.h>
#include <cuda_bf16.h>
#include <cuda_pipeline.h>
#include <math.h>
#include <float.h>

// R15: gap-based two-pass VQ argmin, compacted rescue, FIXED overflow path.
// vs R14 (regressed; k_resc=565us): overflow full-scan was 33k L1-wavefronts
// per row (32-way line fan-out). Fixes: (a) candidate cap 16->32 per half
// (overflow rows ~2.5k -> few hundred); (b) overflow scan now reads a
// TRANSPOSED fp32 e-table coalesced (lane owns codes == lane mod 32, x
// broadcast by shuffle) at 4096 wf/row, with per-code bit-exact ascending-k
// serial fmaf chains.
// Invariant: final code decision bit-identical to R7.

#define NROWS 131072
#define D     128
#define M     1024
#define DECAYF 0.999f
#define EPSF   1e-5f

#define OFF_Q     0L
#define OFF_CODES 16777216L
#define OFF_LOSS  16908288L
#define OFF_PERP  16908289L
#define OFF_EMB   16908290L
#define OFF_CNT   17039362L
#define OFF_W     17040386L
#define OUT_TOTAL 17171458L

#define CHUNKS   8
#define CN       128
#define MARGIN   2e-3f      // candidate window (validated R11-R14)
#define GAP      1.5e-3f    // decided threshold (validated R13/R14)
#define HCAP     32         // candidate slots per half
#define AMB_BLOCKS 1024

// Scratch
__device__ float g_e2[M];
__device__ float g_x2[NROWS];
__device__ float g_counts[M];
__device__ float g_dw[M * D];
__device__ float g_loss;
__device__ __nv_bfloat16 g_ebf[M * D];
__device__ float          g_etr[M * D];              // transposed: [k][code]
__device__ int            g_code[NROWS];
__device__ unsigned short g_cand[(long)NROWS * 64];  // 32 slots per half
__device__ int            g_ambcount;
__device__ unsigned       g_amblist[NROWS];          // bit31 = overflow

__device__ __forceinline__ unsigned smem_u32(const void* p) {
    unsigned a;
    asm("{ .reg .u64 t; cvta.to.shared.u64 t, %1; cvt.u32.u64 %0, t; }"
        : "=r"(a) : "l"(p));
    return a;
}

// ---------------------------------------------------------------------------
// Prep: zero scratch, exact ||e||^2, bf16 image, fp32 transposed image
// ---------------------------------------------------------------------------
__global__ void k_prep(const float* __restrict__ emb) {
    int i = blockIdx.x * 256 + threadIdx.x;       // 0..131071
    if (i < M * D) {
        g_dw[i] = 0.0f;
        g_ebf[i] = __float2bfloat16_rn(emb[i]);
        // transposed image, output-coalesced: i = k*1024 + code
        int k = i >> 10, code = i & 1023;
        g_etr[i] = emb[code * 128 + k];
    }
    if (i < M) {
        g_counts[i] = 0.0f;
        const float* row = emb + i * D;
        float s = 0.0f;
#pragma unroll 8
        for (int d = 0; d < D; d++) { float v = row[d]; s = __fadd_rn(s, __fmul_rn(v, v)); }
        g_e2[i] = s;
    }
    if (i == 0) { g_loss = 0.0f; g_ambcount = 0; }
}

// ---------------------------------------------------------------------------
// ||x||^2 (binade carrier; validated R7)
// ---------------------------------------------------------------------------
__global__ __launch_bounds__(128)
void k_x2(const float* __restrict__ x) {
    __shared__ float sw[2][2];
    const int rsub = threadIdx.x >> 6;
    const int t    = threadIdx.x & 63;
    const long row = (long)blockIdx.x * 2 + rsub;
    float2 v = ((const float2*)(x + row * D))[t];
    float p = __fadd_rn(__fmul_rn(v.x, v.x), __fmul_rn(v.y, v.y));
#pragma unroll
    for (int off = 16; off > 0; off >>= 1)
        p = __fadd_rn(p, __shfl_down_sync(0xffffffffu, p, off));
    if ((t & 31) == 0) sw[rsub][t >> 5] = p;
    __syncthreads();
    if (t == 0) g_x2[row] = __fadd_rn(sw[rsub][0], sw[rsub][1]);
}

// ---------------------------------------------------------------------------
// Pass A: mma.sync bf16 approx scores; per-row (min1,min2,argmin) + cands.
// CTA 256 thr / 128 rows. Scan: thread = (row = tid&127, half = tid>>7).
// ---------------------------------------------------------------------------
#define XES 136
#define SCS 130
#define SM_XS_B   (128 * XES * 2)
#define SM_EB_OFF SM_XS_B
#define SM_EB_B   (128 * XES * 2)
#define SM_SC_OFF (SM_EB_OFF + SM_EB_B)
#define SM_SC_B   (128 * SCS * 2)
#define SM_E2_OFF (SM_SC_OFF + SM_SC_B)
#define SMEMA_BYTES (SM_E2_OFF + 4096)   // 107008

#define LDMX4(r0, r1, r2, r3, a) \
    asm volatile("ldmatrix.sync.aligned.m8n8.x4.shared.b16 {%0,%1,%2,%3}, [%4];" \
        : "=r"(r0), "=r"(r1), "=r"(r2), "=r"(r3) : "r"(a))

#define MMA16816(c, a, b) \
    asm volatile("mma.sync.aligned.m16n8k16.row.col.f32.bf16.bf16.f32 " \
        "{%0,%1,%2,%3}, {%4,%5,%6,%7}, {%8,%9}, {%0,%1,%2,%3};" \
        : "+f"((c)[0]), "+f"((c)[1]), "+f"((c)[2]), "+f"((c)[3]) \
        : "r"((a)[0]), "r"((a)[1]), "r"((a)[2]), "r"((a)[3]), \
          "r"((b)[0]), "r"((b)[1]))

__global__ __launch_bounds__(256, 2)
void k_approx(const float* __restrict__ x) {
    extern __shared__ unsigned char sm[];
    __nv_bfloat16* xs = (__nv_bfloat16*)sm;
    __nv_bfloat16* eb = (__nv_bfloat16*)(sm + SM_EB_OFF);
    __nv_bfloat16* scores = (__nv_bfloat16*)(sm + SM_SC_OFF);
    float* e2s = (float*)(sm + SM_E2_OFF);
    const unsigned xs_a = smem_u32(xs);
    const unsigned eb_a = smem_u32(eb);

    const int tid = threadIdx.x, w = tid >> 5, lane = tid & 31;
    const int R0 = blockIdx.x * 128;

    for (int i = tid; i < 1024; i += 256) e2s[i] = g_e2[i];

    {   // prefetch e chunk 0
        const unsigned char* src = (const unsigned char*)g_ebf;
        unsigned char* dst = (unsigned char*)eb;
        for (int i = tid; i < 2048; i += 256) {
            int r = i >> 4, o = (i & 15) * 16;
            __pipeline_memcpy_async(dst + r * 272 + o, src + r * 256 + o, 16);
        }
        __pipeline_commit();
    }

    {   // x tile -> bf16 smem [row][k]
        const float4* x4 = (const float4*)x;
        for (int i = tid; i < 4096; i += 256) {
            int r = i >> 5, kg = i & 31;
            float4 v = x4[(long)(R0 + r) * 32 + kg];
            __nv_bfloat162 p0 = __floats2bfloat162_rn(v.x, v.y);
            __nv_bfloat162 p1 = __floats2bfloat162_rn(v.z, v.w);
            *(uint2*)&xs[r * XES + kg * 4] =
                make_uint2(*(unsigned*)&p0, *(unsigned*)&p1);
        }
    }

    const int rg = w >> 1;                 // MMA row group (32 rows)
    const int cg = w & 1;                  // MMA code half (64 codes)
    const int rbase = rg * 32;

    // scan state: thread = (srow, half)
    const int srow = tid & 127, half = tid >> 7;
    float rm = FLT_MAX, rm2 = FLT_MAX;
    int am = 0, cnt = 0;
    unsigned short* crow = g_cand + ((long)(R0 + srow)) * 64 + half * HCAP;

    for (int ch = 0; ch < CHUNKS; ch++) {
        __pipeline_wait_prior(0);
        __syncthreads();                   // eb(ch) ready; prev scan done

        float acc[2][8][4];
#pragma unroll
        for (int mt = 0; mt < 2; mt++)
#pragma unroll
            for (int nt = 0; nt < 8; nt++)
#pragma unroll
                for (int q = 0; q < 4; q++) acc[mt][nt][q] = 0.0f;

#pragma unroll
        for (int ks = 0; ks < 8; ks++) {
            unsigned a[2][4];
#pragma unroll
            for (int mt = 0; mt < 2; mt++) {
                int row = rbase + mt * 16 + (lane & 7) + ((lane >> 3) & 1) * 8;
                int ko  = ks * 16 + (lane >> 4) * 8;
                unsigned ad = xs_a + (unsigned)(row * XES + ko) * 2;
                LDMX4(a[mt][0], a[mt][1], a[mt][2], a[mt][3], ad);
            }
            unsigned b[8][2];
#pragma unroll
            for (int p = 0; p < 4; p++) {
                int g = lane >> 3, ri = lane & 7;
                int code = cg * 64 + p * 16 + (g >> 1) * 8 + ri;
                int ko   = ks * 16 + (g & 1) * 8;
                unsigned ad = eb_a + (unsigned)(code * XES + ko) * 2;
                LDMX4(b[2 * p][0], b[2 * p][1], b[2 * p + 1][0], b[2 * p + 1][1], ad);
            }
#pragma unroll
            for (int mt = 0; mt < 2; mt++)
#pragma unroll
                for (int nt = 0; nt < 8; nt++)
                    MMA16816(acc[mt][nt], a[mt], b[nt]);
        }

        // scores (bf16) = e2 - 2*dot
#pragma unroll
        for (int mt = 0; mt < 2; mt++)
#pragma unroll
            for (int nt = 0; nt < 8; nt++) {
                int row = rbase + mt * 16 + (lane >> 2);
                int col = cg * 64 + nt * 8 + (lane & 3) * 2;
                float e2a = e2s[ch * CN + col], e2b = e2s[ch * CN + col + 1];
                __nv_bfloat162 p0 = __floats2bfloat162_rn(
                    fmaf(-2.0f, acc[mt][nt][0], e2a),
                    fmaf(-2.0f, acc[mt][nt][1], e2b));
                __nv_bfloat162 p1 = __floats2bfloat162_rn(
                    fmaf(-2.0f, acc[mt][nt][2], e2a),
                    fmaf(-2.0f, acc[mt][nt][3], e2b));
                *(unsigned*)&scores[row * SCS + col] = *(unsigned*)&p0;
                *(unsigned*)&scores[(row + 8) * SCS + col] = *(unsigned*)&p1;
            }
        __syncthreads();                   // eb free; scores ready

        // prefetch chunk ch+1 (overlaps scan)
        if (ch + 1 < CHUNKS) {
            const unsigned char* src =
                (const unsigned char*)g_ebf + (ch + 1) * CN * 256;
            unsigned char* dst = (unsigned char*)eb;
            for (int i = tid; i < 2048; i += 256) {
                int r = i >> 4, o = (i & 15) * 16;
                __pipeline_memcpy_async(dst + r * 272 + o, src + r * 256 + o, 16);
            }
        }
        __pipeline_commit();

        // scan: each thread scans 64 codes of its half
        {
            const __nv_bfloat16* sr = &scores[srow * SCS + half * 64];
            const int cbase = ch * CN + half * 64;
#pragma unroll 4
            for (int c = 0; c < 64; c++) {
                float s = __bfloat162float(sr[c]);
                if (s < rm + MARGIN) {
                    if (cnt < HCAP) crow[cnt] = (unsigned short)(cbase + c);
                    cnt++;
                }
                if (s < rm) { rm2 = rm; rm = s; am = cbase + c; }
                else if (s < rm2) rm2 = s;
            }
        }
    }

    // sentinel-fill unused slots
    for (int i = (cnt < HCAP ? cnt : HCAP); i < HCAP; i++) crow[i] = 0xFFFF;

    // combine halves -> per-row decision + compaction
    __syncthreads();
    float* c_rm  = (float*)scores;
    float* c_rm2 = c_rm + 256;
    int*   c_am  = (int*)(c_rm2 + 256);
    int*   c_cnt = c_am + 256;
    c_rm[tid] = rm; c_rm2[tid] = rm2; c_am[tid] = am; c_cnt[tid] = cnt;
    __syncthreads();
    if (tid < 128) {
        float rmA = c_rm[tid],  rmB = c_rm[tid + 128];
        float r2A = c_rm2[tid], r2B = c_rm2[tid + 128];
        int   amA = c_am[tid],  amB = c_am[tid + 128];
        float min1, min2; int amW;
        if (rmA <= rmB) { min1 = rmA; amW = amA; min2 = fminf(r2A, rmB); }
        else            { min1 = rmB; amW = amB; min2 = fminf(r2B, rmA); }
        g_code[R0 + tid] = amW;            // approx winner (final if decided)
        if (min2 - min1 <= GAP) {
            int cA = c_cnt[tid], cB = c_cnt[tid + 128];
            unsigned flag = (cA <= HCAP && cB <= HCAP) ? 0u : 0x80000000u;
            int pos = atomicAdd(&g_ambcount, 1);
            g_amblist[pos] = (unsigned)(R0 + tid) | flag;
        }
    }
}

// ---------------------------------------------------------------------------
// Rescue: warp-stride over the compacted ambiguous list. No barriers.
// Candidate rows: lane handles slots (lane, lane+32), row-major float4 chain.
// Overflow rows: coalesced full scan over TRANSPOSED e; lane owns codes
// == lane (mod 32); x broadcast by shuffle; ascending-k serial chains.
// All chains are bit-exact R7 math; lexicographic (s, code) selection.
// ---------------------------------------------------------------------------
__global__ __launch_bounds__(256)
void k_resc(const float* __restrict__ x, const float* __restrict__ emb) {
    const int gw = (blockIdx.x * 256 + threadIdx.x) >> 5;
    const int lane = threadIdx.x & 31;
    const int n = g_ambcount;
    for (int i = gw; i < n; i += AMB_BLOCKS * 8) {
        unsigned e = g_amblist[i];
        const long row = (long)(e & 0x7fffffffu);
        const bool overflow = (e & 0x80000000u) != 0;
        const float4* xr = (const float4*)(x + row * 128);
        const float x2v = g_x2[row];
        float best = FLT_MAX; int bcode = 0x7fffffff;
        if (!overflow) {
#pragma unroll
            for (int sl = 0; sl < 2; sl++) {
                int c16 = g_cand[row * 64 + sl * 32 + lane];
                if (c16 != 0xFFFF) {
                    const float4* er = (const float4*)(emb + (long)c16 * 128);
                    float acc = 0.0f;
#pragma unroll 8
                    for (int k = 0; k < 32; k++) {
                        float4 a = xr[k], b = er[k];
                        acc = fmaf(a.x, b.x, acc);
                        acc = fmaf(a.y, b.y, acc);
                        acc = fmaf(a.z, b.z, acc);
                        acc = fmaf(a.w, b.w, acc);
                    }
                    float s = __fadd_rn(__fadd_rn(g_e2[c16], x2v),
                                        __fmul_rn(-2.0f, acc));
                    if (s < best || (s == best && c16 < bcode)) { best = s; bcode = c16; }
                }
            }
        } else {
            // coalesced exact full scan via g_etr
            float4 xv = xr[lane];          // k = 4*lane .. 4*lane+3
            float acc[32];
#pragma unroll
            for (int t = 0; t < 32; t++) acc[t] = 0.0f;
#pragma unroll 4
            for (int kq = 0; kq < 32; kq++) {
                float xk0 = __shfl_sync(0xffffffffu, xv.x, kq);
                float xk1 = __shfl_sync(0xffffffffu, xv.y, kq);
                float xk2 = __shfl_sync(0xffffffffu, xv.z, kq);
                float xk3 = __shfl_sync(0xffffffffu, xv.w, kq);
                const float* p0 = g_etr + (kq * 4 + 0) * 1024 + lane;
                const float* p1 = g_etr + (kq * 4 + 1) * 1024 + lane;
                const float* p2 = g_etr + (kq * 4 + 2) * 1024 + lane;
                const float* p3 = g_etr + (kq * 4 + 3) * 1024 + lane;
#pragma unroll
                for (int t = 0; t < 32; t++) {
                    int c = t * 32;
                    acc[t] = fmaf(xk0, p0[c], acc[t]);
                    acc[t] = fmaf(xk1, p1[c], acc[t]);
                    acc[t] = fmaf(xk2, p2[c], acc[t]);
                    acc[t] = fmaf(xk3, p3[c], acc[t]);
                }
            }
            // per-lane lexicographic over codes t*32+lane (t ascending =>
            // code ascending for this lane; strict < keeps first index)
#pragma unroll
            for (int t = 0; t < 32; t++) {
                int c = t * 32 + lane;
                float s = __fadd_rn(__fadd_rn(g_e2[c], x2v),
                                    __fmul_rn(-2.0f, acc[t]));
                if (s < best || (s == best && c < bcode)) { best = s; bcode = c; }
            }
        }
#pragma unroll
        for (int o = 16; o > 0; o >>= 1) {
            float ob = __shfl_xor_sync(0xffffffffu, best, o);
            int   oc = __shfl_xor_sync(0xffffffffu, bcode, o);
            if (ob < best || (ob == best && oc < bcode)) { best = ob; bcode = oc; }
        }
        if (lane == 0) g_code[row] = bcode;
    }
}

// ---------------------------------------------------------------------------
// Final epilogue: uniform work, warp per row, lane per float4.
// ---------------------------------------------------------------------------
__global__ __launch_bounds__(256)
void k_final(const float* __restrict__ x, const float* __restrict__ emb,
             float* __restrict__ out_q, float* __restrict__ out_codes,
             int write_aux) {
    __shared__ float sl[8];
    const int w = threadIdx.x >> 5, lane = threadIdx.x & 31;
    const long row = (long)blockIdx.x * 8 + w;
    const int code = g_code[row];

    float4 xv = ((const float4*)x)[row * 32 + lane];
    float4 qv = ((const float4*)emb)[(long)code * 32 + lane];
    float4 o;
    o.x = __fadd_rn(xv.x, __fsub_rn(qv.x, xv.x));
    o.y = __fadd_rn(xv.y, __fsub_rn(qv.y, xv.y));
    o.z = __fadd_rn(xv.z, __fsub_rn(qv.z, xv.z));
    o.w = __fadd_rn(xv.w, __fsub_rn(qv.w, xv.w));
    ((float4*)out_q)[row * 32 + lane] = o;

    float dx = xv.x - qv.x, dy = xv.y - qv.y, dz = xv.z - qv.z, dw_ = xv.w - qv.w;
    float lsum = dx * dx + dy * dy + dz * dz + dw_ * dw_;

    float* dwp = &g_dw[code * 128 + lane * 4];
    atomicAdd(dwp + 0, xv.x);
    atomicAdd(dwp + 1, xv.y);
    atomicAdd(dwp + 2, xv.z);
    atomicAdd(dwp + 3, xv.w);

    if (lane == 0) {
        atomicAdd(&g_counts[code], 1.0f);
        if (write_aux) out_codes[row] = (float)code;
    }
#pragma unroll
    for (int o2 = 16; o2 > 0; o2 >>= 1)
        lsum += __shfl_xor_sync(0xffffffffu, lsum, o2);
    if (lane == 0) sl[w] = lsum;
    __syncthreads();
    if (threadIdx.x == 0) {
        float t = 0.0f;
#pragma unroll
        for (int i = 0; i < 8; i++) t += sl[i];
        atomicAdd(&g_loss, t);
    }
}

// ---------------------------------------------------------------------------
// EMA scalar part (validated R7)
// ---------------------------------------------------------------------------
__global__ void k_ema1(const float* __restrict__ ema_count,
                       float* __restrict__ out_count,
                       float* __restrict__ out_loss,
                       float* __restrict__ out_perp) {
    __shared__ float sred[1024];
    int m = threadIdx.x;
    float cnt = g_counts[m];
    float raw = DECAYF * ema_count[m] + (1.0f - DECAYF) * cnt;
    sred[m] = raw;
    __syncthreads();
    for (int s = 512; s > 0; s >>= 1) {
        if (m < s) sred[m] += sred[m + s];
        __syncthreads();
    }
    float n = sred[0];
    __syncthreads();
    float newc = (raw + EPSF) / (n + 1024.0f * EPSF) * n;
    out_count[m] = newc;

    float p = cnt * (1.0f / 131072.0f);
    sred[m] = -p * logf(p + 1e-10f);
    __syncthreads();
    for (int s = 512; s > 0; s >>= 1) {
        if (m < s) sred[m] += sred[m + s];
        __syncthreads();
    }
    if (m == 0) {
        *out_perp = expf(sred[0]);
        *out_loss = 0.25f * g_loss * (1.0f / 16777216.0f);
    }
}

// ---------------------------------------------------------------------------
// EMA vector part (validated R7)
// ---------------------------------------------------------------------------
__global__ void k_ema2(const float* __restrict__ ema_weight,
                       const float* __restrict__ newc,
                       float* __restrict__ out_w,
                       float* __restrict__ out_emb) {
    int i = blockIdx.x * 256 + threadIdx.x;
    float w = DECAYF * ema_weight[i] + (1.0f - DECAYF) * g_dw[i];
    out_w[i] = w;
    out_emb[i] = w / newc[i >> 7];
}

// ---------------------------------------------------------------------------
extern "C" void kernel_launch(void* const* d_in, const int* in_sizes, int n_in,
                              void* d_out, int out_size) {
    const float* x          = (const float*)d_in[0];
    const float* emb        = (const float*)d_in[1];
    const float* ema_count  = (const float*)d_in[2];
    const float* ema_weight = (const float*)d_in[3];
    float* out = (float*)d_out;

    const int full = (out_size >= (int)OUT_TOTAL) ? 1 : 0;

    cudaFuncSetAttribute(k_approx, cudaFuncAttributeMaxDynamicSharedMemorySize,
                         SMEMA_BYTES);

    k_prep<<<512, 256>>>(emb);
    k_x2<<<NROWS / 2, 128>>>(x);
    k_approx<<<NROWS / 128, 256, SMEMA_BYTES>>>(x);
    k_resc<<<AMB_BLOCKS, 256>>>(x, emb);
    k_final<<<NROWS / 8, 256>>>(x, emb, out + OFF_Q,
                                full ? (out + OFF_CODES) : (out + OFF_Q), full);
    if (full) {
        k_ema1<<<1, 1024>>>(ema_count, out + OFF_CNT, out + OFF_LOSS,
                            out + OFF_PERP);
        k_ema2<<<512, 256>>>(ema_weight, out + OFF_CNT, out + OFF_W,
                             out + OFF_EMB);
    }
}